// round 1
// baseline (speedup 1.0000x reference)
#include <cuda_runtime.h>

// Problem sizes (fixed by the reference)
#define B_SZ 2
#define N_SZ 1024
#define L_SZ 4096
#define C_SZ 1024
#define H_SZ 16
#define D_SZ 64
#define M_KEYS (N_SZ + L_SZ)   // 5120
#define C2 (2 * C_SZ)          // 2048

// Scratch (static device globals — no allocation in kernel_launch)
__device__ float g_Q  [B_SZ * N_SZ * C_SZ];   // [B,N,C]  q (head-interleaved)
__device__ float g_KVo[B_SZ * N_SZ * C2];     // [B,N,2C] kv of x_obj
__device__ float g_KVc[B_SZ * L_SZ * C2];     // [B,L,2C] kv of x_ctx
__device__ float g_Ctx[B_SZ * N_SZ * C_SZ];   // attention output, [B,N,C]

// ---------------------------------------------------------------------------
// SGEMM: C[M,N] = A[M,K] @ B[K,N] (+ bias), all row-major.
// 128x128 tile, BK=8, 256 threads, 8x8 per-thread micro-tile.
// ---------------------------------------------------------------------------
__global__ __launch_bounds__(256)
void sgemm128(int M, int N, int K,
              const float* __restrict__ A, const float* __restrict__ B,
              float* __restrict__ C, const float* __restrict__ bias)
{
    const int BM = 128, BN = 128, BK = 8, TM = 8, TN = 8;
    __shared__ float As[BK][BM];   // A tile, transposed
    __shared__ float Bs[BK][BN];

    const int tid  = threadIdx.x;
    const int crow = blockIdx.y, ccol = blockIdx.x;

    A += (size_t)crow * BM * K;
    B += (size_t)ccol * BN;
    C += (size_t)crow * BM * N + (size_t)ccol * BN;

    const int arow = tid >> 1;            // 0..127
    const int acol = (tid & 1) * 4;       // 0 or 4
    const int brow = tid >> 5;            // 0..7
    const int bcol = (tid & 31) * 4;      // 0..124
    const int trow = (tid >> 4) * TM;     // 0..120
    const int tcol = (tid & 15) * TN;     // 0..120

    float acc[TM][TN] = {};
    float regM[TM], regN[TN];

    for (int k0 = 0; k0 < K; k0 += BK) {
        float4 a4 = *reinterpret_cast<const float4*>(A + (size_t)arow * K + acol);
        As[acol + 0][arow] = a4.x;
        As[acol + 1][arow] = a4.y;
        As[acol + 2][arow] = a4.z;
        As[acol + 3][arow] = a4.w;
        *reinterpret_cast<float4*>(&Bs[brow][bcol]) =
            *reinterpret_cast<const float4*>(B + (size_t)brow * N + bcol);
        __syncthreads();
        A += BK;
        B += (size_t)BK * N;
        #pragma unroll
        for (int k = 0; k < BK; ++k) {
            #pragma unroll
            for (int i = 0; i < TM; ++i) regM[i] = As[k][trow + i];
            #pragma unroll
            for (int j = 0; j < TN; ++j) regN[j] = Bs[k][tcol + j];
            #pragma unroll
            for (int i = 0; i < TM; ++i)
                #pragma unroll
                for (int j = 0; j < TN; ++j)
                    acc[i][j] += regM[i] * regN[j];
        }
        __syncthreads();
    }

    #pragma unroll
    for (int i = 0; i < TM; ++i) {
        #pragma unroll
        for (int j = 0; j < TN; j += 4) {
            float4 v;
            v.x = acc[i][j + 0];
            v.y = acc[i][j + 1];
            v.z = acc[i][j + 2];
            v.w = acc[i][j + 3];
            if (bias != nullptr) {
                int gc = ccol * BN + tcol + j;
                v.x += bias[gc + 0];
                v.y += bias[gc + 1];
                v.z += bias[gc + 2];
                v.w += bias[gc + 3];
            }
            *reinterpret_cast<float4*>(C + (size_t)(trow + i) * N + tcol + j) = v;
        }
    }
}

// ---------------------------------------------------------------------------
// Flash attention (fp32), d=64. Block handles 64 queries of one (b,h).
// Iterates 80 key tiles of 64 (16 from x_obj kv, 64 from x_ctx kv).
// 256 threads, 4x4 register micro-tiles for both S=QK^T and O+=PV.
// Online softmax with per-row (m, l) carried in registers (replicated
// across the 16 threads that own the row).
// ---------------------------------------------------------------------------
#define KP_LD 68   // padded row length (floats) for the K/P shared tile

__global__ __launch_bounds__(256)
void flash_attn(const float* __restrict__ Q,
                const float* __restrict__ KVo,
                const float* __restrict__ KVc,
                float* __restrict__ Ctx)
{
    extern __shared__ float sm[];
    float* Qs  = sm;                    // [64][64]   q transposed ([d][m]), pre-scaled
    float* KPs = sm + 64 * 64;          // [64][KP_LD] K as [d][n], then P^T as [n][m]
    float* Vs  = KPs + 64 * KP_LD;      // [64][64]   V natural [n][d]

    const int tid = threadIdx.x;
    const int qt  = blockIdx.x;   // query tile 0..15
    const int h   = blockIdx.y;   // head
    const int b   = blockIdx.z;   // batch

    const float scale = 0.125f;   // d^-0.5 = 1/8

    // Load Q tile, transposed + pre-scaled
    const float* Qg = Q + ((size_t)b * N_SZ + (size_t)qt * 64) * C_SZ + h * D_SZ;
    #pragma unroll
    for (int r = 0; r < 4; ++r) {
        int fid = tid + r * 256;     // 0..1023 float4 slots
        int m   = fid >> 4;          // 0..63
        int ds  = (fid & 15) * 4;    // 0..60
        float4 v = *reinterpret_cast<const float4*>(Qg + (size_t)m * C_SZ + ds);
        Qs[(ds + 0) * 64 + m] = v.x * scale;
        Qs[(ds + 1) * 64 + m] = v.y * scale;
        Qs[(ds + 2) * 64 + m] = v.z * scale;
        Qs[(ds + 3) * 64 + m] = v.w * scale;
    }

    const int trow = (tid >> 4) * 4;   // query rows owned
    const int tcol = (tid & 15) * 4;   // key cols / d cols owned

    float o[4][4] = {};
    float mi[4], li[4];
    #pragma unroll
    for (int i = 0; i < 4; ++i) { mi[i] = -1e30f; li[i] = 0.0f; }

    for (int kt = 0; kt < M_KEYS / 64; ++kt) {
        const float* Kg;
        if (kt < N_SZ / 64)
            Kg = KVo + ((size_t)b * N_SZ + (size_t)kt * 64) * C2 + h * D_SZ;
        else
            Kg = KVc + ((size_t)b * L_SZ + ((size_t)kt * 64 - N_SZ)) * C2 + h * D_SZ;
        const float* Vg = Kg + C_SZ;

        __syncthreads();  // previous iteration's KPs/Vs consumers done (also covers Qs on kt=0)

        // Load K tile transposed -> KPs[d][n]; V tile natural -> Vs[n][d]
        #pragma unroll
        for (int r = 0; r < 4; ++r) {
            int fid = tid + r * 256;
            int n   = fid >> 4;
            int ds  = (fid & 15) * 4;
            float4 kv = *reinterpret_cast<const float4*>(Kg + (size_t)n * C2 + ds);
            KPs[(ds + 0) * KP_LD + n] = kv.x;
            KPs[(ds + 1) * KP_LD + n] = kv.y;
            KPs[(ds + 2) * KP_LD + n] = kv.z;
            KPs[(ds + 3) * KP_LD + n] = kv.w;
            float4 vv = *reinterpret_cast<const float4*>(Vg + (size_t)n * C2 + ds);
            *reinterpret_cast<float4*>(&Vs[n * 64 + ds]) = vv;
        }
        __syncthreads();

        // S = (scaled Q) @ K^T  — 4x4 in registers
        float s[4][4] = {};
        #pragma unroll
        for (int dd = 0; dd < D_SZ; ++dd) {
            float4 rm4 = *reinterpret_cast<const float4*>(&Qs[dd * 64 + trow]);
            float4 rn4 = *reinterpret_cast<const float4*>(&KPs[dd * KP_LD + tcol]);
            float rm[4] = {rm4.x, rm4.y, rm4.z, rm4.w};
            float rn[4] = {rn4.x, rn4.y, rn4.z, rn4.w};
            #pragma unroll
            for (int i = 0; i < 4; ++i)
                #pragma unroll
                for (int j = 0; j < 4; ++j)
                    s[i][j] += rm[i] * rn[j];
        }

        // Online softmax (row groups of 16 threads; shfl_xor within 16 lanes)
        float p[4][4];
        float corr[4];
        #pragma unroll
        for (int i = 0; i < 4; ++i) {
            float rmax = s[i][0];
            #pragma unroll
            for (int j = 1; j < 4; ++j) rmax = fmaxf(rmax, s[i][j]);
            #pragma unroll
            for (int off = 8; off; off >>= 1)
                rmax = fmaxf(rmax, __shfl_xor_sync(0xffffffffu, rmax, off));
            float mnew = fmaxf(mi[i], rmax);
            corr[i] = __expf(mi[i] - mnew);
            float rsum = 0.0f;
            #pragma unroll
            for (int j = 0; j < 4; ++j) {
                p[i][j] = __expf(s[i][j] - mnew);
                rsum += p[i][j];
            }
            #pragma unroll
            for (int off = 8; off; off >>= 1)
                rsum += __shfl_xor_sync(0xffffffffu, rsum, off);
            li[i] = li[i] * corr[i] + rsum;
            mi[i] = mnew;
        }
        #pragma unroll
        for (int i = 0; i < 4; ++i)
            #pragma unroll
            for (int j = 0; j < 4; ++j)
                o[i][j] *= corr[i];

        __syncthreads();  // everyone done reading KPs as K
        // Write P transposed into KPs: Pt[n][m]
        #pragma unroll
        for (int i = 0; i < 4; ++i)
            #pragma unroll
            for (int j = 0; j < 4; ++j)
                KPs[(tcol + j) * KP_LD + (trow + i)] = p[i][j];
        __syncthreads();

        // O += P @ V
        #pragma unroll 8
        for (int n = 0; n < 64; ++n) {
            float4 rm4 = *reinterpret_cast<const float4*>(&KPs[n * KP_LD + trow]);
            float4 rn4 = *reinterpret_cast<const float4*>(&Vs[n * 64 + tcol]);
            float rm[4] = {rm4.x, rm4.y, rm4.z, rm4.w};
            float rn[4] = {rn4.x, rn4.y, rn4.z, rn4.w};
            #pragma unroll
            for (int i = 0; i < 4; ++i)
                #pragma unroll
                for (int j = 0; j < 4; ++j)
                    o[i][j] += rm[i] * rn[j];
        }
    }

    // Epilogue: normalize by l and write out (layout already [B,N,h*d+d] = [B,N,C])
    float* Og = Ctx + ((size_t)b * N_SZ + (size_t)qt * 64) * C_SZ + h * D_SZ;
    #pragma unroll
    for (int i = 0; i < 4; ++i) {
        float inv = 1.0f / li[i];
        float4 v;
        v.x = o[i][0] * inv;
        v.y = o[i][1] * inv;
        v.z = o[i][2] * inv;
        v.w = o[i][3] * inv;
        *reinterpret_cast<float4*>(Og + (size_t)(trow + i) * C_SZ + tcol) = v;
    }
}

// ---------------------------------------------------------------------------
extern "C" void kernel_launch(void* const* d_in, const int* in_sizes, int n_in,
                              void* d_out, int out_size)
{
    const float* x_obj = (const float*)d_in[0];  // [2,1024,1024]
    const float* x_ctx = (const float*)d_in[1];  // [2,4096,1024]
    const float* Wq    = (const float*)d_in[2];  // [1024,1024]
    const float* Wkv   = (const float*)d_in[3];  // [1024,2048]
    const float* Wproj = (const float*)d_in[4];  // [1024,1024]
    const float* bproj = (const float*)d_in[5];  // [1024]
    float* out = (float*)d_out;                  // [2,1024,1024]

    float *pQ, *pKVo, *pKVc, *pCtx;
    cudaGetSymbolAddress((void**)&pQ,   g_Q);
    cudaGetSymbolAddress((void**)&pKVo, g_KVo);
    cudaGetSymbolAddress((void**)&pKVc, g_KVc);
    cudaGetSymbolAddress((void**)&pCtx, g_Ctx);

    const int attn_smem = (64 * 64 + 64 * KP_LD + 64 * 64) * (int)sizeof(float);
    cudaFuncSetAttribute(flash_attn, cudaFuncAttributeMaxDynamicSharedMemorySize, attn_smem);

    // Q = x_obj @ Wq                    [2048,1024]x[1024,1024]
    sgemm128<<<dim3(1024 / 128, 2048 / 128), 256>>>(2048, 1024, 1024, x_obj, Wq, pQ, nullptr);
    // KVo = x_obj @ Wkv                 [2048,1024]x[1024,2048]
    sgemm128<<<dim3(2048 / 128, 2048 / 128), 256>>>(2048, 2048, 1024, x_obj, Wkv, pKVo, nullptr);
    // KVc = x_ctx @ Wkv                 [8192,1024]x[1024,2048]
    sgemm128<<<dim3(2048 / 128, 8192 / 128), 256>>>(8192, 2048, 1024, x_ctx, Wkv, pKVc, nullptr);
    // Attention
    flash_attn<<<dim3(N_SZ / 64, H_SZ, B_SZ), 256, attn_smem>>>(pQ, pKVo, pKVc, pCtx);
    // out = Ctx @ Wproj + bproj
    sgemm128<<<dim3(1024 / 128, 2048 / 128), 256>>>(2048, 1024, 1024, pCtx, Wproj, out, bproj);
}

// round 3
// speedup vs baseline: 1.5586x; 1.5586x over previous
#include <cuda_runtime.h>
#include <cstdint>

// Problem sizes (fixed by the reference)
#define B_SZ 2
#define N_SZ 1024
#define L_SZ 4096
#define C_SZ 1024
#define H_SZ 16
#define D_SZ 64
#define M_KEYS (N_SZ + L_SZ)   // 5120
#define C2 (2 * C_SZ)          // 2048

// Scratch (static device globals — no allocation in kernel_launch)
__device__ float g_Q   [B_SZ * N_SZ * C_SZ];   // [B,N,C]
__device__ float g_KVo [B_SZ * N_SZ * C2];     // [B,N,2C]
__device__ float g_KVc [B_SZ * L_SZ * C2];     // [B,L,2C]
__device__ float g_Ctx [B_SZ * N_SZ * C_SZ];   // attention output
__device__ float g_WqT   [C_SZ * C_SZ];        // Wq^T    [N,K]
__device__ float g_WkvT  [C2 * C_SZ];          // Wkv^T   [2C,C]
__device__ float g_WprojT[C_SZ * C_SZ];        // Wproj^T [N,K]

// ---------------------------------------------------------------------------
// Helpers (all sm_80-era PTX — assembles under compute_103 virtual arch)
// ---------------------------------------------------------------------------
__device__ __forceinline__ uint32_t smem_u32(const void* p) {
    uint32_t a;
    asm("{ .reg .u64 t; cvta.to.shared.u64 t, %1; cvt.u32.u64 %0, t; }"
        : "=r"(a) : "l"(p));
    return a;
}
__device__ __forceinline__ uint32_t f2tf32(float f) {
    uint32_t r;
    asm("cvt.rna.tf32.f32 %0, %1;" : "=r"(r) : "f"(f));
    return r;
}
__device__ __forceinline__ void cp16(uint32_t dst, const float* src) {
    asm volatile("cp.async.ca.shared.global [%0], [%1], 16;"
                 :: "r"(dst), "l"(src));
}
__device__ __forceinline__ void mma_tf32(float* d, const uint32_t* a,
                                         uint32_t b0, uint32_t b1) {
    asm volatile(
        "mma.sync.aligned.m16n8k8.row.col.f32.tf32.tf32.f32 "
        "{%0,%1,%2,%3}, {%4,%5,%6,%7}, {%8,%9}, {%0,%1,%2,%3};"
        : "+f"(d[0]), "+f"(d[1]), "+f"(d[2]), "+f"(d[3])
        : "r"(a[0]), "r"(a[1]), "r"(a[2]), "r"(a[3]), "r"(b0), "r"(b1));
}

// ---------------------------------------------------------------------------
// Weight transpose: out[c][r] = in[r][c].  in: [R, Ccols], out: [Ccols, R]
// ---------------------------------------------------------------------------
__global__ __launch_bounds__(256)
void transpose_w(const float* __restrict__ in, float* __restrict__ out,
                 int R, int Ccols)
{
    __shared__ float t[32][33];
    int c0 = blockIdx.x * 32, r0 = blockIdx.y * 32;
    #pragma unroll
    for (int j = threadIdx.y; j < 32; j += 8)
        t[j][threadIdx.x] = in[(size_t)(r0 + j) * Ccols + c0 + threadIdx.x];
    __syncthreads();
    #pragma unroll
    for (int j = threadIdx.y; j < 32; j += 8)
        out[(size_t)(c0 + j) * R + r0 + threadIdx.x] = t[threadIdx.x][j];
}

// ---------------------------------------------------------------------------
// TF32 tensor-core GEMM:  C[M,N] = A[M,K] @ BT[N,K]^T  (+ bias)
// 128x128 CTA tile, BK=16, 8 warps (warp tile 32x64), m16n8k8 tf32 mma,
// cp.async double-buffered SMEM, pad-20 rows (conflict-free frag loads).
// ---------------------------------------------------------------------------
#define BKC 16
#define APAD 20
#define TILE_W (128 * APAD)     // words per A or B stage

__global__ __launch_bounds__(256, 2)
void gemm_mma(int M, int N, int K,
              const float* __restrict__ A, const float* __restrict__ BT,
              float* __restrict__ C, const float* __restrict__ bias)
{
    __shared__ float sm[4 * TILE_W];   // [stage][A|B] : 40960 B

    const int tid  = threadIdx.x;
    const int wid  = tid >> 5, lane = tid & 31;
    const int grp  = lane >> 2, qid = lane & 3;
    const int bm   = blockIdx.y * 128, bn = blockIdx.x * 128;
    const int wm   = (wid & 3) * 32;     // warp M offset in tile
    const int wn   = (wid >> 2) * 64;    // warp N offset in tile

    const uint32_t sbase = smem_u32(sm);
    const int m_ld = tid >> 2;           // 0..63
    const int q_ld = (tid & 3) * 4;      // 0,4,8,12

    float acc[2][8][4];
    #pragma unroll
    for (int i = 0; i < 2; ++i)
        #pragma unroll
        for (int j = 0; j < 8; ++j)
            #pragma unroll
            for (int q = 0; q < 4; ++q) acc[i][j][q] = 0.0f;

    const float* Abase = A  + (size_t)bm * K;
    const float* Bbase = BT + (size_t)bn * K;

    auto load_tile = [&](int c, int stg) {
        uint32_t as = sbase + (uint32_t)(stg * 2 * TILE_W) * 4u;
        uint32_t bs = as + (uint32_t)TILE_W * 4u;
        const float* Ag = Abase + (size_t)c * BKC;
        const float* Bg = Bbase + (size_t)c * BKC;
        #pragma unroll
        for (int i = 0; i < 2; ++i) {
            int m = m_ld + i * 64;
            cp16(as + (uint32_t)(m * APAD + q_ld) * 4u, Ag + (size_t)m * K + q_ld);
            cp16(bs + (uint32_t)(m * APAD + q_ld) * 4u, Bg + (size_t)m * K + q_ld);
        }
    };

    load_tile(0, 0);
    asm volatile("cp.async.commit_group;");

    const int NC = K / BKC;
    for (int c = 0; c < NC; ++c) {
        if (c + 1 < NC) {
            load_tile(c + 1, (c + 1) & 1);
            asm volatile("cp.async.commit_group;");
            asm volatile("cp.async.wait_group 1;");
        } else {
            asm volatile("cp.async.wait_group 0;");
        }
        __syncthreads();

        const float* As = sm + (c & 1) * 2 * TILE_W;
        const float* Bs = As + TILE_W;
        #pragma unroll
        for (int kk = 0; kk < BKC; kk += 8) {
            uint32_t at[2][4];
            #pragma unroll
            for (int mf = 0; mf < 2; ++mf) {
                int r0 = wm + mf * 16 + grp;
                at[mf][0] = f2tf32(As[r0 * APAD + kk + qid]);
                at[mf][1] = f2tf32(As[(r0 + 8) * APAD + kk + qid]);
                at[mf][2] = f2tf32(As[r0 * APAD + kk + qid + 4]);
                at[mf][3] = f2tf32(As[(r0 + 8) * APAD + kk + qid + 4]);
            }
            #pragma unroll
            for (int nf = 0; nf < 8; ++nf) {
                int cn = wn + nf * 8 + grp;
                uint32_t b0 = f2tf32(Bs[cn * APAD + kk + qid]);
                uint32_t b1 = f2tf32(Bs[cn * APAD + kk + qid + 4]);
                mma_tf32(acc[0][nf], at[0], b0, b1);
                mma_tf32(acc[1][nf], at[1], b0, b1);
            }
        }
        __syncthreads();
    }

    // Epilogue
    #pragma unroll
    for (int mf = 0; mf < 2; ++mf) {
        int r0 = bm + wm + mf * 16 + grp;
        #pragma unroll
        for (int nf = 0; nf < 8; ++nf) {
            int cc = bn + wn + nf * 8 + qid * 2;
            float b0 = 0.0f, b1 = 0.0f;
            if (bias != nullptr) { b0 = bias[cc]; b1 = bias[cc + 1]; }
            float2 v0; v0.x = acc[mf][nf][0] + b0; v0.y = acc[mf][nf][1] + b1;
            float2 v1; v1.x = acc[mf][nf][2] + b0; v1.y = acc[mf][nf][3] + b1;
            *reinterpret_cast<float2*>(C + (size_t)r0 * N + cc) = v0;
            *reinterpret_cast<float2*>(C + (size_t)(r0 + 8) * N + cc) = v1;
        }
    }
}

// ---------------------------------------------------------------------------
// Flash attention (fp32 SIMT) — unchanged (known correct).
// ---------------------------------------------------------------------------
#define KP_LD 68

__global__ __launch_bounds__(256)
void flash_attn(const float* __restrict__ Q,
                const float* __restrict__ KVo,
                const float* __restrict__ KVc,
                float* __restrict__ Ctx)
{
    extern __shared__ float smf[];
    float* Qs  = smf;
    float* KPs = smf + 64 * 64;
    float* Vs  = KPs + 64 * KP_LD;

    const int tid = threadIdx.x;
    const int qt  = blockIdx.x;
    const int h   = blockIdx.y;
    const int b   = blockIdx.z;

    const float scale = 0.125f;

    const float* Qg = Q + ((size_t)b * N_SZ + (size_t)qt * 64) * C_SZ + h * D_SZ;
    #pragma unroll
    for (int r = 0; r < 4; ++r) {
        int fid = tid + r * 256;
        int m   = fid >> 4;
        int ds  = (fid & 15) * 4;
        float4 v = *reinterpret_cast<const float4*>(Qg + (size_t)m * C_SZ + ds);
        Qs[(ds + 0) * 64 + m] = v.x * scale;
        Qs[(ds + 1) * 64 + m] = v.y * scale;
        Qs[(ds + 2) * 64 + m] = v.z * scale;
        Qs[(ds + 3) * 64 + m] = v.w * scale;
    }

    const int trow = (tid >> 4) * 4;
    const int tcol = (tid & 15) * 4;

    float o[4][4] = {};
    float mi[4], li[4];
    #pragma unroll
    for (int i = 0; i < 4; ++i) { mi[i] = -1e30f; li[i] = 0.0f; }

    for (int kt = 0; kt < M_KEYS / 64; ++kt) {
        const float* Kg;
        if (kt < N_SZ / 64)
            Kg = KVo + ((size_t)b * N_SZ + (size_t)kt * 64) * C2 + h * D_SZ;
        else
            Kg = KVc + ((size_t)b * L_SZ + ((size_t)kt * 64 - N_SZ)) * C2 + h * D_SZ;
        const float* Vg = Kg + C_SZ;

        __syncthreads();

        #pragma unroll
        for (int r = 0; r < 4; ++r) {
            int fid = tid + r * 256;
            int n   = fid >> 4;
            int ds  = (fid & 15) * 4;
            float4 kv = *reinterpret_cast<const float4*>(Kg + (size_t)n * C2 + ds);
            KPs[(ds + 0) * KP_LD + n] = kv.x;
            KPs[(ds + 1) * KP_LD + n] = kv.y;
            KPs[(ds + 2) * KP_LD + n] = kv.z;
            KPs[(ds + 3) * KP_LD + n] = kv.w;
            float4 vv = *reinterpret_cast<const float4*>(Vg + (size_t)n * C2 + ds);
            *reinterpret_cast<float4*>(&Vs[n * 64 + ds]) = vv;
        }
        __syncthreads();

        float s[4][4] = {};
        #pragma unroll
        for (int dd = 0; dd < D_SZ; ++dd) {
            float4 rm4 = *reinterpret_cast<const float4*>(&Qs[dd * 64 + trow]);
            float4 rn4 = *reinterpret_cast<const float4*>(&KPs[dd * KP_LD + tcol]);
            float rm[4] = {rm4.x, rm4.y, rm4.z, rm4.w};
            float rn[4] = {rn4.x, rn4.y, rn4.z, rn4.w};
            #pragma unroll
            for (int i = 0; i < 4; ++i)
                #pragma unroll
                for (int j = 0; j < 4; ++j)
                    s[i][j] += rm[i] * rn[j];
        }

        float p[4][4];
        float corr[4];
        #pragma unroll
        for (int i = 0; i < 4; ++i) {
            float rmax = s[i][0];
            #pragma unroll
            for (int j = 1; j < 4; ++j) rmax = fmaxf(rmax, s[i][j]);
            #pragma unroll
            for (int off = 8; off; off >>= 1)
                rmax = fmaxf(rmax, __shfl_xor_sync(0xffffffffu, rmax, off));
            float mnew = fmaxf(mi[i], rmax);
            corr[i] = __expf(mi[i] - mnew);
            float rsum = 0.0f;
            #pragma unroll
            for (int j = 0; j < 4; ++j) {
                p[i][j] = __expf(s[i][j] - mnew);
                rsum += p[i][j];
            }
            #pragma unroll
            for (int off = 8; off; off >>= 1)
                rsum += __shfl_xor_sync(0xffffffffu, rsum, off);
            li[i] = li[i] * corr[i] + rsum;
            mi[i] = mnew;
        }
        #pragma unroll
        for (int i = 0; i < 4; ++i)
            #pragma unroll
            for (int j = 0; j < 4; ++j)
                o[i][j] *= corr[i];

        __syncthreads();
        #pragma unroll
        for (int i = 0; i < 4; ++i)
            #pragma unroll
            for (int j = 0; j < 4; ++j)
                KPs[(tcol + j) * KP_LD + (trow + i)] = p[i][j];
        __syncthreads();

        #pragma unroll 8
        for (int n = 0; n < 64; ++n) {
            float4 rm4 = *reinterpret_cast<const float4*>(&KPs[n * KP_LD + trow]);
            float4 rn4 = *reinterpret_cast<const float4*>(&Vs[n * 64 + tcol]);
            float rm[4] = {rm4.x, rm4.y, rm4.z, rm4.w};
            float rn[4] = {rn4.x, rn4.y, rn4.z, rn4.w};
            #pragma unroll
            for (int i = 0; i < 4; ++i)
                #pragma unroll
                for (int j = 0; j < 4; ++j)
                    o[i][j] += rm[i] * rn[j];
        }
    }

    float* Og = Ctx + ((size_t)b * N_SZ + (size_t)qt * 64) * C_SZ + h * D_SZ;
    #pragma unroll
    for (int i = 0; i < 4; ++i) {
        float inv = 1.0f / li[i];
        float4 v;
        v.x = o[i][0] * inv;
        v.y = o[i][1] * inv;
        v.z = o[i][2] * inv;
        v.w = o[i][3] * inv;
        *reinterpret_cast<float4*>(Og + (size_t)(trow + i) * C_SZ + tcol) = v;
    }
}

// ---------------------------------------------------------------------------
extern "C" void kernel_launch(void* const* d_in, const int* in_sizes, int n_in,
                              void* d_out, int out_size)
{
    const float* x_obj = (const float*)d_in[0];
    const float* x_ctx = (const float*)d_in[1];
    const float* Wq    = (const float*)d_in[2];
    const float* Wkv   = (const float*)d_in[3];
    const float* Wproj = (const float*)d_in[4];
    const float* bproj = (const float*)d_in[5];
    float* out = (float*)d_out;

    float *pQ, *pKVo, *pKVc, *pCtx, *pWqT, *pWkvT, *pWprojT;
    cudaGetSymbolAddress((void**)&pQ,      g_Q);
    cudaGetSymbolAddress((void**)&pKVo,    g_KVo);
    cudaGetSymbolAddress((void**)&pKVc,    g_KVc);
    cudaGetSymbolAddress((void**)&pCtx,    g_Ctx);
    cudaGetSymbolAddress((void**)&pWqT,    g_WqT);
    cudaGetSymbolAddress((void**)&pWkvT,   g_WkvT);
    cudaGetSymbolAddress((void**)&pWprojT, g_WprojT);

    const int attn_smem = (64 * 64 + 64 * KP_LD + 64 * 64) * (int)sizeof(float);
    cudaFuncSetAttribute(flash_attn, cudaFuncAttributeMaxDynamicSharedMemorySize, attn_smem);

    // Weight transposes ([K,N] -> [N,K])
    transpose_w<<<dim3(C_SZ / 32, C_SZ / 32), dim3(32, 8)>>>(Wq, pWqT, C_SZ, C_SZ);
    transpose_w<<<dim3(C2 / 32, C_SZ / 32), dim3(32, 8)>>>(Wkv, pWkvT, C_SZ, C2);
    transpose_w<<<dim3(C_SZ / 32, C_SZ / 32), dim3(32, 8)>>>(Wproj, pWprojT, C_SZ, C_SZ);

    // Projections (tensor-core tf32)
    gemm_mma<<<dim3(1024 / 128, 2048 / 128), 256>>>(
        2048, 1024, 1024, x_obj, pWqT, pQ, nullptr);
    gemm_mma<<<dim3(2048 / 128, 2048 / 128), 256>>>(
        2048, 2048, 1024, x_obj, pWkvT, pKVo, nullptr);
    gemm_mma<<<dim3(2048 / 128, 8192 / 128), 256>>>(
        8192, 2048, 1024, x_ctx, pWkvT, pKVc, nullptr);

    // Attention (fp32 SIMT, unchanged)
    flash_attn<<<dim3(N_SZ / 64, H_SZ, B_SZ), 256, attn_smem>>>(pQ, pKVo, pKVc, pCtx);

    // Output projection + bias (tensor-core tf32)
    gemm_mma<<<dim3(1024 / 128, 2048 / 128), 256>>>(
        2048, 1024, 1024, pCtx, pWprojT, out, bproj);
}

// round 4
// speedup vs baseline: 3.3386x; 2.1420x over previous
#include <cuda_runtime.h>
#include <cstdint>

// Problem sizes (fixed by the reference)
#define B_SZ 2
#define N_SZ 1024
#define L_SZ 4096
#define C_SZ 1024
#define H_SZ 16
#define D_SZ 64
#define M_KEYS (N_SZ + L_SZ)   // 5120
#define C2 (2 * C_SZ)          // 2048

// Scratch (static device globals — no allocation in kernel_launch)
__device__ float g_Q   [B_SZ * N_SZ * C_SZ];   // [B,N,C]
__device__ float g_KVo [B_SZ * N_SZ * C2];     // [B,N,2C]
__device__ float g_KVc [B_SZ * L_SZ * C2];     // [B,L,2C]
__device__ float g_Ctx [B_SZ * N_SZ * C_SZ];   // attention output
__device__ float g_WqT   [C_SZ * C_SZ];        // Wq^T    [N,K]
__device__ float g_WkvT  [C2 * C_SZ];          // Wkv^T   [2C,C]
__device__ float g_WprojT[C_SZ * C_SZ];        // Wproj^T [N,K]

// ---------------------------------------------------------------------------
// Helpers (sm_80-era PTX — assembles under compute_103 virtual arch)
// ---------------------------------------------------------------------------
__device__ __forceinline__ uint32_t smem_u32(const void* p) {
    uint32_t a;
    asm("{ .reg .u64 t; cvta.to.shared.u64 t, %1; cvt.u32.u64 %0, t; }"
        : "=r"(a) : "l"(p));
    return a;
}
__device__ __forceinline__ uint32_t f2tf32(float f) {
    uint32_t r;
    asm("cvt.rna.tf32.f32 %0, %1;" : "=r"(r) : "f"(f));
    return r;
}
__device__ __forceinline__ float f2tf32f(float f) {
    return __uint_as_float(f2tf32(f));
}
__device__ __forceinline__ void cp16(uint32_t dst, const float* src) {
    asm volatile("cp.async.ca.shared.global [%0], [%1], 16;"
                 :: "r"(dst), "l"(src));
}
__device__ __forceinline__ void mma_tf32(float* d, const uint32_t* a,
                                         uint32_t b0, uint32_t b1) {
    asm volatile(
        "mma.sync.aligned.m16n8k8.row.col.f32.tf32.tf32.f32 "
        "{%0,%1,%2,%3}, {%4,%5,%6,%7}, {%8,%9}, {%0,%1,%2,%3};"
        : "+f"(d[0]), "+f"(d[1]), "+f"(d[2]), "+f"(d[3])
        : "r"(a[0]), "r"(a[1]), "r"(a[2]), "r"(a[3]), "r"(b0), "r"(b1));
}

// ---------------------------------------------------------------------------
// Weight transpose: out[c][r] = in[r][c].  in: [R, Ccols], out: [Ccols, R]
// ---------------------------------------------------------------------------
__global__ __launch_bounds__(256)
void transpose_w(const float* __restrict__ in, float* __restrict__ out,
                 int R, int Ccols)
{
    __shared__ float t[32][33];
    int c0 = blockIdx.x * 32, r0 = blockIdx.y * 32;
    #pragma unroll
    for (int j = threadIdx.y; j < 32; j += 8)
        t[j][threadIdx.x] = in[(size_t)(r0 + j) * Ccols + c0 + threadIdx.x];
    __syncthreads();
    #pragma unroll
    for (int j = threadIdx.y; j < 32; j += 8)
        out[(size_t)(c0 + j) * R + r0 + threadIdx.x] = t[threadIdx.x][j];
}

// ---------------------------------------------------------------------------
// TF32 tensor-core GEMM (unchanged from round 3 — known correct)
// ---------------------------------------------------------------------------
#define BKC 16
#define APAD 20
#define TILE_W (128 * APAD)

__global__ __launch_bounds__(256, 2)
void gemm_mma(int M, int N, int K,
              const float* __restrict__ A, const float* __restrict__ BT,
              float* __restrict__ C, const float* __restrict__ bias)
{
    __shared__ float sm[4 * TILE_W];

    const int tid  = threadIdx.x;
    const int wid  = tid >> 5, lane = tid & 31;
    const int grp  = lane >> 2, qid = lane & 3;
    const int bm   = blockIdx.y * 128, bn = blockIdx.x * 128;
    const int wm   = (wid & 3) * 32;
    const int wn   = (wid >> 2) * 64;

    const uint32_t sbase = smem_u32(sm);
    const int m_ld = tid >> 2;
    const int q_ld = (tid & 3) * 4;

    float acc[2][8][4];
    #pragma unroll
    for (int i = 0; i < 2; ++i)
        #pragma unroll
        for (int j = 0; j < 8; ++j)
            #pragma unroll
            for (int q = 0; q < 4; ++q) acc[i][j][q] = 0.0f;

    const float* Abase = A  + (size_t)bm * K;
    const float* Bbase = BT + (size_t)bn * K;

    auto load_tile = [&](int c, int stg) {
        uint32_t as = sbase + (uint32_t)(stg * 2 * TILE_W) * 4u;
        uint32_t bs = as + (uint32_t)TILE_W * 4u;
        const float* Ag = Abase + (size_t)c * BKC;
        const float* Bg = Bbase + (size_t)c * BKC;
        #pragma unroll
        for (int i = 0; i < 2; ++i) {
            int m = m_ld + i * 64;
            cp16(as + (uint32_t)(m * APAD + q_ld) * 4u, Ag + (size_t)m * K + q_ld);
            cp16(bs + (uint32_t)(m * APAD + q_ld) * 4u, Bg + (size_t)m * K + q_ld);
        }
    };

    load_tile(0, 0);
    asm volatile("cp.async.commit_group;");

    const int NC = K / BKC;
    for (int c = 0; c < NC; ++c) {
        if (c + 1 < NC) {
            load_tile(c + 1, (c + 1) & 1);
            asm volatile("cp.async.commit_group;");
            asm volatile("cp.async.wait_group 1;");
        } else {
            asm volatile("cp.async.wait_group 0;");
        }
        __syncthreads();

        const float* As = sm + (c & 1) * 2 * TILE_W;
        const float* Bs = As + TILE_W;
        #pragma unroll
        for (int kk = 0; kk < BKC; kk += 8) {
            uint32_t at[2][4];
            #pragma unroll
            for (int mf = 0; mf < 2; ++mf) {
                int r0 = wm + mf * 16 + grp;
                at[mf][0] = f2tf32(As[r0 * APAD + kk + qid]);
                at[mf][1] = f2tf32(As[(r0 + 8) * APAD + kk + qid]);
                at[mf][2] = f2tf32(As[r0 * APAD + kk + qid + 4]);
                at[mf][3] = f2tf32(As[(r0 + 8) * APAD + kk + qid + 4]);
            }
            #pragma unroll
            for (int nf = 0; nf < 8; ++nf) {
                int cn = wn + nf * 8 + grp;
                uint32_t b0 = f2tf32(Bs[cn * APAD + kk + qid]);
                uint32_t b1 = f2tf32(Bs[cn * APAD + kk + qid + 4]);
                mma_tf32(acc[0][nf], at[0], b0, b1);
                mma_tf32(acc[1][nf], at[1], b0, b1);
            }
        }
        __syncthreads();
    }

    #pragma unroll
    for (int mf = 0; mf < 2; ++mf) {
        int r0 = bm + wm + mf * 16 + grp;
        #pragma unroll
        for (int nf = 0; nf < 8; ++nf) {
            int cc = bn + wn + nf * 8 + qid * 2;
            float b0 = 0.0f, b1 = 0.0f;
            if (bias != nullptr) { b0 = bias[cc]; b1 = bias[cc + 1]; }
            float2 v0; v0.x = acc[mf][nf][0] + b0; v0.y = acc[mf][nf][1] + b1;
            float2 v1; v1.x = acc[mf][nf][2] + b0; v1.y = acc[mf][nf][3] + b1;
            *reinterpret_cast<float2*>(C + (size_t)r0 * N + cc) = v0;
            *reinterpret_cast<float2*>(C + (size_t)(r0 + 8) * N + cc) = v1;
        }
    }
}

// ---------------------------------------------------------------------------
// Flash attention on tensor cores (tf32 mma.sync).
// CTA: 256 threads (8 warps), 128-query tile, 64-key tiles, d=64.
// Warp w owns query rows [w*16, w*16+16). Online softmax in accumulator
// fragments; P goes through SMEM (C-frag -> A-frag relayout).
// Pads: Qs/Ks/Ps 68 (frag banks 4*grp+qid all-distinct),
//       Vs 72 (PV B-frag banks 8*qid+grp all-distinct).
// ---------------------------------------------------------------------------
#define QPAD 68
#define VPAD 72
#define FA_SMEM ((128 * QPAD + 64 * QPAD + 64 * VPAD + 128 * QPAD) * 4)

__global__ __launch_bounds__(256, 2)
void flash_mma(const float* __restrict__ Q,
               const float* __restrict__ KVo,
               const float* __restrict__ KVc,
               float* __restrict__ Ctx)
{
    extern __shared__ float sm[];
    float* Qs = sm;                       // [128][QPAD]
    float* Ks = Qs + 128 * QPAD;          // [64][QPAD]   (keys x d)
    float* Vs = Ks + 64 * QPAD;           // [64][VPAD]   (keys x d)
    float* Ps = Vs + 64 * VPAD;           // [128][QPAD]

    const int tid  = threadIdx.x;
    const int wid  = tid >> 5, lane = tid & 31;
    const int grp  = lane >> 2, qid = lane & 3;
    const int wm   = wid * 16;
    const int qt   = blockIdx.x;   // 0..7 (128-row q tiles)
    const int h    = blockIdx.y;
    const int b    = blockIdx.z;

    const float scale = 0.125f;

    // Load Q tile [128][64], scale + tf32-round once
    const float* Qg = Q + ((size_t)b * N_SZ + (size_t)qt * 128) * C_SZ + h * D_SZ;
    #pragma unroll
    for (int r = 0; r < 8; ++r) {
        int fid = tid + r * 256;          // 0..2047 float4 slots
        int m   = fid >> 4;
        int ds  = (fid & 15) * 4;
        float4 v = *reinterpret_cast<const float4*>(Qg + (size_t)m * C_SZ + ds);
        float4 w;
        w.x = f2tf32f(v.x * scale);
        w.y = f2tf32f(v.y * scale);
        w.z = f2tf32f(v.z * scale);
        w.w = f2tf32f(v.w * scale);
        *reinterpret_cast<float4*>(&Qs[m * QPAD + ds]) = w;
    }

    float o[8][4];
    #pragma unroll
    for (int nf = 0; nf < 8; ++nf)
        #pragma unroll
        for (int q = 0; q < 4; ++q) o[nf][q] = 0.0f;
    float mi[2] = {-1e30f, -1e30f};
    float li[2] = {0.0f, 0.0f};

    for (int kt = 0; kt < M_KEYS / 64; ++kt) {
        const float* Kg;
        if (kt < N_SZ / 64)
            Kg = KVo + ((size_t)b * N_SZ + (size_t)kt * 64) * C2 + h * D_SZ;
        else
            Kg = KVc + ((size_t)b * L_SZ + ((size_t)kt * 64 - N_SZ)) * C2 + h * D_SZ;
        const float* Vg = Kg + C_SZ;

        __syncthreads();   // prior iteration done with Ks/Vs/Ps

        // Load K -> Ks[key][d], V -> Vs[key][d] (tf32-rounded)
        #pragma unroll
        for (int r = 0; r < 4; ++r) {
            int fid = tid + r * 256;      // 0..1023
            int n   = fid >> 4;
            int ds  = (fid & 15) * 4;
            float4 kv = *reinterpret_cast<const float4*>(Kg + (size_t)n * C2 + ds);
            float4 kw;
            kw.x = f2tf32f(kv.x); kw.y = f2tf32f(kv.y);
            kw.z = f2tf32f(kv.z); kw.w = f2tf32f(kv.w);
            *reinterpret_cast<float4*>(&Ks[n * QPAD + ds]) = kw;
            float4 vv = *reinterpret_cast<const float4*>(Vg + (size_t)n * C2 + ds);
            float4 vw;
            vw.x = f2tf32f(vv.x); vw.y = f2tf32f(vv.y);
            vw.z = f2tf32f(vv.z); vw.w = f2tf32f(vv.w);
            *reinterpret_cast<float4*>(&Vs[n * VPAD + ds]) = vw;
        }
        __syncthreads();

        // S = Qs @ Ks^T : per-warp m16 x n64 x k64
        float s[8][4];
        #pragma unroll
        for (int nf = 0; nf < 8; ++nf)
            #pragma unroll
            for (int q = 0; q < 4; ++q) s[nf][q] = 0.0f;

        #pragma unroll
        for (int kk = 0; kk < 8; ++kk) {
            uint32_t a[4];
            const int r0 = (wm + grp) * QPAD + kk * 8 + qid;
            const int r1 = (wm + grp + 8) * QPAD + kk * 8 + qid;
            a[0] = __float_as_uint(Qs[r0]);
            a[1] = __float_as_uint(Qs[r1]);
            a[2] = __float_as_uint(Qs[r0 + 4]);
            a[3] = __float_as_uint(Qs[r1 + 4]);
            #pragma unroll
            for (int nf = 0; nf < 8; ++nf) {
                const int cn = (nf * 8 + grp) * QPAD + kk * 8 + qid;
                uint32_t b0 = __float_as_uint(Ks[cn]);
                uint32_t b1 = __float_as_uint(Ks[cn + 4]);
                mma_tf32(s[nf], a, b0, b1);
            }
        }

        // Online softmax (rows grp and grp+8 of this warp's 16)
        float mx0 = -1e30f, mx1 = -1e30f;
        #pragma unroll
        for (int nf = 0; nf < 8; ++nf) {
            mx0 = fmaxf(mx0, fmaxf(s[nf][0], s[nf][1]));
            mx1 = fmaxf(mx1, fmaxf(s[nf][2], s[nf][3]));
        }
        #pragma unroll
        for (int off = 1; off < 4; off <<= 1) {
            mx0 = fmaxf(mx0, __shfl_xor_sync(0xffffffffu, mx0, off));
            mx1 = fmaxf(mx1, __shfl_xor_sync(0xffffffffu, mx1, off));
        }
        float mnew0 = fmaxf(mi[0], mx0);
        float mnew1 = fmaxf(mi[1], mx1);
        float corr0 = __expf(mi[0] - mnew0);
        float corr1 = __expf(mi[1] - mnew1);
        float sum0 = 0.0f, sum1 = 0.0f;
        #pragma unroll
        for (int nf = 0; nf < 8; ++nf) {
            s[nf][0] = __expf(s[nf][0] - mnew0);
            s[nf][1] = __expf(s[nf][1] - mnew0);
            s[nf][2] = __expf(s[nf][2] - mnew1);
            s[nf][3] = __expf(s[nf][3] - mnew1);
            sum0 += s[nf][0] + s[nf][1];
            sum1 += s[nf][2] + s[nf][3];
        }
        #pragma unroll
        for (int off = 1; off < 4; off <<= 1) {
            sum0 += __shfl_xor_sync(0xffffffffu, sum0, off);
            sum1 += __shfl_xor_sync(0xffffffffu, sum1, off);
        }
        li[0] = li[0] * corr0 + sum0;
        li[1] = li[1] * corr1 + sum1;
        mi[0] = mnew0;
        mi[1] = mnew1;
        #pragma unroll
        for (int nf = 0; nf < 8; ++nf) {
            o[nf][0] *= corr0;
            o[nf][1] *= corr0;
            o[nf][2] *= corr1;
            o[nf][3] *= corr1;
        }

        // P -> SMEM (tf32-rounded), relayout C-frag -> A-frag
        #pragma unroll
        for (int nf = 0; nf < 8; ++nf) {
            float2 p0, p1;
            p0.x = f2tf32f(s[nf][0]); p0.y = f2tf32f(s[nf][1]);
            p1.x = f2tf32f(s[nf][2]); p1.y = f2tf32f(s[nf][3]);
            *reinterpret_cast<float2*>(&Ps[(wm + grp) * QPAD + nf * 8 + qid * 2]) = p0;
            *reinterpret_cast<float2*>(&Ps[(wm + grp + 8) * QPAD + nf * 8 + qid * 2]) = p1;
        }
        __syncthreads();

        // O += P @ V : per-warp m16 x n64(d) x k64(keys)
        #pragma unroll
        for (int kk = 0; kk < 8; ++kk) {
            uint32_t a[4];
            const int r0 = (wm + grp) * QPAD + kk * 8 + qid;
            const int r1 = (wm + grp + 8) * QPAD + kk * 8 + qid;
            a[0] = __float_as_uint(Ps[r0]);
            a[1] = __float_as_uint(Ps[r1]);
            a[2] = __float_as_uint(Ps[r0 + 4]);
            a[3] = __float_as_uint(Ps[r1 + 4]);
            #pragma unroll
            for (int nf = 0; nf < 8; ++nf) {
                const int cb = (kk * 8 + qid) * VPAD + nf * 8 + grp;
                uint32_t b0 = __float_as_uint(Vs[cb]);
                uint32_t b1 = __float_as_uint(Vs[cb + 4 * VPAD]);
                mma_tf32(o[nf], a, b0, b1);
            }
        }
    }

    // Epilogue: normalize and store
    const float inv0 = 1.0f / li[0];
    const float inv1 = 1.0f / li[1];
    float* Og = Ctx + ((size_t)b * N_SZ + (size_t)qt * 128) * C_SZ + h * D_SZ;
    #pragma unroll
    for (int nf = 0; nf < 8; ++nf) {
        int col = nf * 8 + qid * 2;
        float2 v0, v1;
        v0.x = o[nf][0] * inv0; v0.y = o[nf][1] * inv0;
        v1.x = o[nf][2] * inv1; v1.y = o[nf][3] * inv1;
        *reinterpret_cast<float2*>(Og + (size_t)(wm + grp) * C_SZ + col) = v0;
        *reinterpret_cast<float2*>(Og + (size_t)(wm + grp + 8) * C_SZ + col) = v1;
    }
}

// ---------------------------------------------------------------------------
extern "C" void kernel_launch(void* const* d_in, const int* in_sizes, int n_in,
                              void* d_out, int out_size)
{
    const float* x_obj = (const float*)d_in[0];
    const float* x_ctx = (const float*)d_in[1];
    const float* Wq    = (const float*)d_in[2];
    const float* Wkv   = (const float*)d_in[3];
    const float* Wproj = (const float*)d_in[4];
    const float* bproj = (const float*)d_in[5];
    float* out = (float*)d_out;

    float *pQ, *pKVo, *pKVc, *pCtx, *pWqT, *pWkvT, *pWprojT;
    cudaGetSymbolAddress((void**)&pQ,      g_Q);
    cudaGetSymbolAddress((void**)&pKVo,    g_KVo);
    cudaGetSymbolAddress((void**)&pKVc,    g_KVc);
    cudaGetSymbolAddress((void**)&pCtx,    g_Ctx);
    cudaGetSymbolAddress((void**)&pWqT,    g_WqT);
    cudaGetSymbolAddress((void**)&pWkvT,   g_WkvT);
    cudaGetSymbolAddress((void**)&pWprojT, g_WprojT);

    cudaFuncSetAttribute(flash_mma, cudaFuncAttributeMaxDynamicSharedMemorySize, FA_SMEM);

    // Weight transposes ([K,N] -> [N,K])
    transpose_w<<<dim3(C_SZ / 32, C_SZ / 32), dim3(32, 8)>>>(Wq, pWqT, C_SZ, C_SZ);
    transpose_w<<<dim3(C2 / 32, C_SZ / 32), dim3(32, 8)>>>(Wkv, pWkvT, C_SZ, C2);
    transpose_w<<<dim3(C_SZ / 32, C_SZ / 32), dim3(32, 8)>>>(Wproj, pWprojT, C_SZ, C_SZ);

    // Projections (tensor-core tf32)
    gemm_mma<<<dim3(1024 / 128, 2048 / 128), 256>>>(
        2048, 1024, 1024, x_obj, pWqT, pQ, nullptr);
    gemm_mma<<<dim3(2048 / 128, 2048 / 128), 256>>>(
        2048, 2048, 1024, x_obj, pWkvT, pKVo, nullptr);
    gemm_mma<<<dim3(2048 / 128, 8192 / 128), 256>>>(
        8192, 2048, 1024, x_ctx, pWkvT, pKVc, nullptr);

    // Attention (tensor-core tf32 flash)
    flash_mma<<<dim3(N_SZ / 128, H_SZ, B_SZ), 256, FA_SMEM>>>(pQ, pKVo, pKVc, pCtx);

    // Output projection + bias (tensor-core tf32)
    gemm_mma<<<dim3(1024 / 128, 2048 / 128), 256>>>(
        2048, 1024, 1024, pCtx, pWprojT, out, bproj);
}